// round 4
// baseline (speedup 1.0000x reference)
#include <cuda_runtime.h>
#include <cstdint>

#define N_ROWS 131072
#define DIM    256
#define KCB    1024

#define BM 128
#define BN 128
#define BD 32
#define PAD 4

__device__ float  g_cnorm[KCB];
__device__ float  g_zn[N_ROWS];
__device__ int    g_ids[N_ROWS];
__device__ double g_loss;

// ---------------------------------------------------------------------------
// Row norms, replicating XLA's row-reduction order:
//   warp per row, lane t accumulates elements t + 32*i (i ascending),
//   square via separate mul+add (XLA emits fmul+fadd, no FMA contraction),
//   then shfl_down tree with offsets 16,8,4,2,1.
// ---------------------------------------------------------------------------
__device__ __forceinline__ float row_sumsq_warp(const float* __restrict__ row,
                                                int lane) {
    float s = 0.f;
#pragma unroll
    for (int i = 0; i < DIM / 32; ++i) {
        float v = row[lane + i * 32];
        s = __fadd_rn(s, __fmul_rn(v, v));   // no FMA: match XLA mul+add
    }
#pragma unroll
    for (int o = 16; o > 0; o >>= 1)
        s = __fadd_rn(s, __shfl_down_sync(0xFFFFFFFFu, s, o));
    return s;
}

__global__ void norms_kernel(const float* __restrict__ z,
                             const float* __restrict__ cb) {
    int warp = (blockIdx.x * blockDim.x + threadIdx.x) >> 5;
    int lane = threadIdx.x & 31;
    if (warp == 0 && lane == 0) g_loss = 0.0;
    if (warp < N_ROWS) {
        float s = row_sumsq_warp(z + (size_t)warp * DIM, lane);
        if (lane == 0) g_zn[warp] = s;
    }
    if (warp < KCB) {
        float s = row_sumsq_warp(cb + (size_t)warp * DIM, lane);
        if (lane == 0) g_cnorm[warp] = s;
    }
}

// ---------------------------------------------------------------------------
// Fused fp32 distance GEMM + argmin.
// dot accumulation: single register per (row,code), strictly ascending d,
// FFMA with RN -- bit-matches cuBLAS SIMT SGEMM accumulation.
// score chain: s = fl(zn - 2*dot) ; v = fl(s + cn)   (matches XLA fusion)
// strict '<' over ascending k + lowest-index tie-break == jnp.argmin.
// ---------------------------------------------------------------------------
__global__ void __launch_bounds__(256, 2)
argmin_kernel(const float* __restrict__ z, const float* __restrict__ cb) {
    __shared__ __align__(16) float zs[BD][BM + PAD];
    __shared__ __align__(16) float cs[BD][BN + PAD];
    __shared__ float zn_s[BM];

    const int tid = threadIdx.x;
    const int tx = tid & 15;
    const int ty = tid >> 4;
    const int blockRow = blockIdx.x * BM;

    if (tid < BM) zn_s[tid] = g_zn[blockRow + tid];

    float bestv[8];
    int   besti[8];
#pragma unroll
    for (int i = 0; i < 8; ++i) { bestv[i] = 3.4e38f; besti[i] = 0; }

    const int c4 = tid & 7;
    const int r0 = tid >> 3;

#pragma unroll 1
    for (int kt = 0; kt < KCB; kt += BN) {
        float acc[8][8];
#pragma unroll
        for (int i = 0; i < 8; ++i)
#pragma unroll
            for (int j = 0; j < 8; ++j) acc[i][j] = 0.f;

#pragma unroll 1
        for (int dt = 0; dt < DIM; dt += BD) {
            __syncthreads();
#pragma unroll
            for (int p = 0; p < 4; ++p) {
                int r = p * 32 + r0;
                float4 v = *(const float4*)&z[(size_t)(blockRow + r) * DIM + dt + c4 * 4];
                zs[c4 * 4 + 0][r] = v.x; zs[c4 * 4 + 1][r] = v.y;
                zs[c4 * 4 + 2][r] = v.z; zs[c4 * 4 + 3][r] = v.w;
                float4 w = *(const float4*)&cb[(size_t)(kt + r) * DIM + dt + c4 * 4];
                cs[c4 * 4 + 0][r] = w.x; cs[c4 * 4 + 1][r] = w.y;
                cs[c4 * 4 + 2][r] = w.z; cs[c4 * 4 + 3][r] = w.w;
            }
            __syncthreads();

#pragma unroll 8
            for (int d = 0; d < BD; ++d) {
                float za[8];
                float4 a0 = *(const float4*)&zs[d][ty * 8];
                float4 a1 = *(const float4*)&zs[d][ty * 8 + 4];
                za[0] = a0.x; za[1] = a0.y; za[2] = a0.z; za[3] = a0.w;
                za[4] = a1.x; za[5] = a1.y; za[6] = a1.z; za[7] = a1.w;
                float cbv[8];
#pragma unroll
                for (int j = 0; j < 8; ++j) cbv[j] = cs[d][tx + 16 * j];
#pragma unroll
                for (int i = 0; i < 8; ++i)
#pragma unroll
                    for (int j = 0; j < 8; ++j)
                        acc[i][j] = fmaf(za[i], cbv[j], acc[i][j]);
            }
        }

#pragma unroll
        for (int j = 0; j < 8; ++j) {
            int kk = kt + tx + 16 * j;
            float cn = g_cnorm[kk];
#pragma unroll
            for (int i = 0; i < 8; ++i) {
                float s = fmaf(-2.f, acc[i][j], zn_s[ty * 8 + i]); // fl(zn-2e)
                float v = __fadd_rn(s, cn);                        // fl(s+cn)
                if (v < bestv[i]) { bestv[i] = v; besti[i] = kk; }
            }
        }
    }

    __syncthreads();
    float* redv = &zs[0][0];
    int*   redi = (int*)&cs[0][0];
#pragma unroll
    for (int i = 0; i < 8; ++i) {
        redv[(ty * 8 + i) * 16 + tx] = bestv[i];
        redi[(ty * 8 + i) * 16 + tx] = besti[i];
    }
    __syncthreads();
    if (tid < BM) {
        float bv = redv[tid * 16];
        int   bi = redi[tid * 16];
#pragma unroll
        for (int t = 1; t < 16; ++t) {
            float v = redv[tid * 16 + t];
            int   ii = redi[tid * 16 + t];
            if (v < bv || (v == bv && ii < bi)) { bv = v; bi = ii; }
        }
        g_ids[blockRow + tid] = bi;
    }
}

// ---------------------------------------------------------------------------
// Outputs: z | z_q_st = z + (z_q - z) | ids | loss
// ---------------------------------------------------------------------------
__global__ void output_kernel(const float* __restrict__ z,
                              const float* __restrict__ cb,
                              float* __restrict__ out) {
    const size_t ND = (size_t)N_ROWS * DIM;
    int gtid = blockIdx.x * blockDim.x + threadIdx.x;
    size_t base = (size_t)gtid * 4;

    float local = 0.f;
    if (base < ND) {
        int n = (int)(base / DIM);
        int d = (int)(base % DIM);
        float4 zv = *(const float4*)&z[base];
        int id = g_ids[n];
        float4 cv = *(const float4*)&cb[(size_t)id * DIM + d];
        *(float4*)&out[base] = zv;
        float tx_ = __fadd_rn(cv.x, -zv.x), ty_ = __fadd_rn(cv.y, -zv.y);
        float tz_ = __fadd_rn(cv.z, -zv.z), tw_ = __fadd_rn(cv.w, -zv.w);
        float4 st;
        st.x = __fadd_rn(zv.x, tx_); st.y = __fadd_rn(zv.y, ty_);
        st.z = __fadd_rn(zv.z, tz_); st.w = __fadd_rn(zv.w, tw_);
        *(float4*)&out[ND + base] = st;
        local = tx_ * tx_ + ty_ * ty_ + tz_ * tz_ + tw_ * tw_;
    }
    if (gtid < N_ROWS) out[2 * ND + gtid] = (float)g_ids[gtid];

    __shared__ float warp_s[8];
#pragma unroll
    for (int o = 16; o > 0; o >>= 1)
        local += __shfl_down_sync(0xFFFFFFFFu, local, o);
    if ((threadIdx.x & 31) == 0) warp_s[threadIdx.x >> 5] = local;
    __syncthreads();
    if (threadIdx.x < 8) {
        float v = warp_s[threadIdx.x];
#pragma unroll
        for (int o = 4; o > 0; o >>= 1)
            v += __shfl_down_sync(0xFFu, v, o);
        if (threadIdx.x == 0 && v != 0.f) atomicAdd(&g_loss, (double)v);
    }
}

__global__ void finalize_kernel(float* __restrict__ out) {
    const size_t ND = (size_t)N_ROWS * DIM;
    out[2 * ND + N_ROWS] = (float)(1.25 * g_loss / (double)ND);
}

// ---------------------------------------------------------------------------
extern "C" void kernel_launch(void* const* d_in, const int* in_sizes, int n_in,
                              void* d_out, int out_size) {
    const float* z  = (const float*)d_in[0];
    const float* cb = (const float*)d_in[1];
    float* out = (float*)d_out;

    norms_kernel<<<(N_ROWS * 32 + 255) / 256, 256>>>(z, cb);
    argmin_kernel<<<N_ROWS / BM, 256>>>(z, cb);
    const size_t ND = (size_t)N_ROWS * DIM;
    int nblk = (int)((ND / 4 + 255) / 256);
    output_kernel<<<nblk, 256>>>(z, cb, out);
    finalize_kernel<<<1, 1>>>(out);
}

// round 5
// speedup vs baseline: 1.1033x; 1.1033x over previous
#include <cuda_runtime.h>
#include <cstdint>

#define N_ROWS 131072
#define DIM    256
#define KCB    1024

#define BM 128
#define BN 128
#define BD 32
#define PAD 4

__device__ float  g_cnorm[KCB];
__device__ float  g_zn[N_ROWS];
__device__ int    g_ids[N_ROWS];
__device__ double g_loss;

typedef unsigned long long u64;

// packed dual-fp32 FMA: d.lo = a.lo*b.lo + c.lo ; d.hi = a.hi*b.hi + c.hi
// Each half is an independent IEEE fp32 RN FMA == scalar FFMA bitwise.
#define FMA_F32X2(d, a, b, c) \
    asm("fma.rn.f32x2 %0, %1, %2, %3;" : "=l"(d) : "l"(a), "l"(b), "l"(c))
#define DUP_F32X2(d, x) \
    asm("mov.b64 %0, {%1, %1};" : "=l"(d) : "r"(x))

__device__ __forceinline__ float lo32(u64 v) { return __uint_as_float((unsigned)(v & 0xFFFFFFFFu)); }
__device__ __forceinline__ float hi32(u64 v) { return __uint_as_float((unsigned)(v >> 32)); }

// ---------------------------------------------------------------------------
// Row norms, replicating XLA's row-reduction order (bit-exact, keep as-is):
// warp/row, lane t sums elems t+32i (mul+add, no FMA), shfl_down 16..1.
// ---------------------------------------------------------------------------
__device__ __forceinline__ float row_sumsq_warp(const float* __restrict__ row,
                                                int lane) {
    float s = 0.f;
#pragma unroll
    for (int i = 0; i < DIM / 32; ++i) {
        float v = row[lane + i * 32];
        s = __fadd_rn(s, __fmul_rn(v, v));
    }
#pragma unroll
    for (int o = 16; o > 0; o >>= 1)
        s = __fadd_rn(s, __shfl_down_sync(0xFFFFFFFFu, s, o));
    return s;
}

__global__ void norms_kernel(const float* __restrict__ z,
                             const float* __restrict__ cb) {
    int warp = (blockIdx.x * blockDim.x + threadIdx.x) >> 5;
    int lane = threadIdx.x & 31;
    if (warp == 0 && lane == 0) g_loss = 0.0;
    if (warp < N_ROWS) {
        float s = row_sumsq_warp(z + (size_t)warp * DIM, lane);
        if (lane == 0) g_zn[warp] = s;
    }
    if (warp < KCB) {
        float s = row_sumsq_warp(cb + (size_t)warp * DIM, lane);
        if (lane == 0) g_cnorm[warp] = s;
    }
}

// ---------------------------------------------------------------------------
// Fused fp32 distance GEMM + argmin, FFMA2 (f32x2) mainloop.
// Row pairs (i,i+1) share a packed accumulator; per-(row,k) chain is still
// single-register, strictly ascending d, RN -- bitwise == scalar version.
// ---------------------------------------------------------------------------
__global__ void __launch_bounds__(256, 2)
argmin_kernel(const float* __restrict__ z, const float* __restrict__ cb) {
    __shared__ __align__(16) float zs[BD][BM + PAD];
    __shared__ __align__(16) float cs[BD][BN + PAD];
    __shared__ float zn_s[BM];

    const int tid = threadIdx.x;
    const int tx = tid & 15;
    const int ty = tid >> 4;
    const int blockRow = blockIdx.x * BM;

    if (tid < BM) zn_s[tid] = g_zn[blockRow + tid];

    float bestv[8];
    int   besti[8];
#pragma unroll
    for (int i = 0; i < 8; ++i) { bestv[i] = 3.4e38f; besti[i] = 0; }

    const int c4 = tid & 7;
    const int r0 = tid >> 3;

#pragma unroll 1
    for (int kt = 0; kt < KCB; kt += BN) {
        u64 acc[4][8];   // [row-pair p][col j], packed (row ty*8+2p, +1)
#pragma unroll
        for (int p = 0; p < 4; ++p)
#pragma unroll
            for (int j = 0; j < 8; ++j) acc[p][j] = 0ull;

#pragma unroll 1
        for (int dt = 0; dt < DIM; dt += BD) {
            __syncthreads();
#pragma unroll
            for (int q = 0; q < 4; ++q) {
                int r = q * 32 + r0;
                float4 v = *(const float4*)&z[(size_t)(blockRow + r) * DIM + dt + c4 * 4];
                zs[c4 * 4 + 0][r] = v.x; zs[c4 * 4 + 1][r] = v.y;
                zs[c4 * 4 + 2][r] = v.z; zs[c4 * 4 + 3][r] = v.w;
                float4 w = *(const float4*)&cb[(size_t)(kt + r) * DIM + dt + c4 * 4];
                cs[c4 * 4 + 0][r] = w.x; cs[c4 * 4 + 1][r] = w.y;
                cs[c4 * 4 + 2][r] = w.z; cs[c4 * 4 + 3][r] = w.w;
            }
            __syncthreads();

#pragma unroll 8
            for (int d = 0; d < BD; ++d) {
                u64 zap[4];
#pragma unroll
                for (int p = 0; p < 4; ++p)
                    zap[p] = *(const u64*)&zs[d][ty * 8 + 2 * p];  // (z_i, z_{i+1})
                u64 cdup[8];
#pragma unroll
                for (int j = 0; j < 8; ++j) {
                    float c = cs[d][tx + 16 * j];
                    DUP_F32X2(cdup[j], __float_as_uint(c));
                }
#pragma unroll
                for (int p = 0; p < 4; ++p)
#pragma unroll
                    for (int j = 0; j < 8; ++j)
                        FMA_F32X2(acc[p][j], zap[p], cdup[j], acc[p][j]);
            }
        }

        // epilogue: identical scalar rounding chain; j ascending => k ascending,
        // strict '<' reproduces argmin lowest-index tie-break.
#pragma unroll
        for (int j = 0; j < 8; ++j) {
            int kk = kt + tx + 16 * j;
            float cn = g_cnorm[kk];
#pragma unroll
            for (int p = 0; p < 4; ++p) {
                float a0 = lo32(acc[p][j]);
                float a1 = hi32(acc[p][j]);
                int i0 = 2 * p, i1 = 2 * p + 1;
                float s0 = fmaf(-2.f, a0, zn_s[ty * 8 + i0]);
                float v0 = __fadd_rn(s0, cn);
                if (v0 < bestv[i0]) { bestv[i0] = v0; besti[i0] = kk; }
                float s1 = fmaf(-2.f, a1, zn_s[ty * 8 + i1]);
                float v1 = __fadd_rn(s1, cn);
                if (v1 < bestv[i1]) { bestv[i1] = v1; besti[i1] = kk; }
            }
        }
    }

    __syncthreads();
    float* redv = &zs[0][0];
    int*   redi = (int*)&cs[0][0];
#pragma unroll
    for (int i = 0; i < 8; ++i) {
        redv[(ty * 8 + i) * 16 + tx] = bestv[i];
        redi[(ty * 8 + i) * 16 + tx] = besti[i];
    }
    __syncthreads();
    if (tid < BM) {
        float bv = redv[tid * 16];
        int   bi = redi[tid * 16];
#pragma unroll
        for (int t = 1; t < 16; ++t) {
            float v = redv[tid * 16 + t];
            int   ii = redi[tid * 16 + t];
            if (v < bv || (v == bv && ii < bi)) { bv = v; bi = ii; }
        }
        g_ids[blockRow + tid] = bi;
    }
}

// ---------------------------------------------------------------------------
// Outputs: z | z_q_st = z + (z_q - z) | ids | loss
// ---------------------------------------------------------------------------
__global__ void output_kernel(const float* __restrict__ z,
                              const float* __restrict__ cb,
                              float* __restrict__ out) {
    const size_t ND = (size_t)N_ROWS * DIM;
    int gtid = blockIdx.x * blockDim.x + threadIdx.x;
    size_t base = (size_t)gtid * 4;

    float local = 0.f;
    if (base < ND) {
        int n = (int)(base / DIM);
        int d = (int)(base % DIM);
        float4 zv = *(const float4*)&z[base];
        int id = g_ids[n];
        float4 cv = *(const float4*)&cb[(size_t)id * DIM + d];
        *(float4*)&out[base] = zv;
        float tx_ = __fadd_rn(cv.x, -zv.x), ty_ = __fadd_rn(cv.y, -zv.y);
        float tz_ = __fadd_rn(cv.z, -zv.z), tw_ = __fadd_rn(cv.w, -zv.w);
        float4 st;
        st.x = __fadd_rn(zv.x, tx_); st.y = __fadd_rn(zv.y, ty_);
        st.z = __fadd_rn(zv.z, tz_); st.w = __fadd_rn(zv.w, tw_);
        *(float4*)&out[ND + base] = st;
        local = tx_ * tx_ + ty_ * ty_ + tz_ * tz_ + tw_ * tw_;
    }
    if (gtid < N_ROWS) out[2 * ND + gtid] = (float)g_ids[gtid];

    __shared__ float warp_s[8];
#pragma unroll
    for (int o = 16; o > 0; o >>= 1)
        local += __shfl_down_sync(0xFFFFFFFFu, local, o);
    if ((threadIdx.x & 31) == 0) warp_s[threadIdx.x >> 5] = local;
    __syncthreads();
    if (threadIdx.x < 8) {
        float v = warp_s[threadIdx.x];
#pragma unroll
        for (int o = 4; o > 0; o >>= 1)
            v += __shfl_down_sync(0xFFu, v, o);
        if (threadIdx.x == 0 && v != 0.f) atomicAdd(&g_loss, (double)v);
    }
}

__global__ void finalize_kernel(float* __restrict__ out) {
    const size_t ND = (size_t)N_ROWS * DIM;
    out[2 * ND + N_ROWS] = (float)(1.25 * g_loss / (double)ND);
}

// ---------------------------------------------------------------------------
extern "C" void kernel_launch(void* const* d_in, const int* in_sizes, int n_in,
                              void* d_out, int out_size) {
    const float* z  = (const float*)d_in[0];
    const float* cb = (const float*)d_in[1];
    float* out = (float*)d_out;

    norms_kernel<<<(N_ROWS * 32 + 255) / 256, 256>>>(z, cb);
    argmin_kernel<<<N_ROWS / BM, 256>>>(z, cb);
    const size_t ND = (size_t)N_ROWS * DIM;
    int nblk = (int)((ND / 4 + 255) / 256);
    output_kernel<<<nblk, 256>>>(z, cb, out);
    finalize_kernel<<<1, 1>>>(out);
}

// round 8
// speedup vs baseline: 1.6419x; 1.4882x over previous
#include <cuda_runtime.h>
#include <cuda_bf16.h>
#include <mma.h>
#include <cstdint>

using namespace nvcuda;

#define N_ROWS 131072
#define DIM    256
#define KCB    1024
#define DELTA  1.25e-3f

#define BM 128
#define BN 128
#define BD 32
#define PAD 4

__device__ float  g_cnorm[KCB];
__device__ float  g_zn[N_ROWS];
__device__ int    g_ids[N_ROWS];
__device__ int    g_flagged[N_ROWS];
__device__ int    g_nflag;
__device__ double g_loss;

typedef unsigned long long u64;

#define FMA_F32X2(d, a, b, c) \
    asm("fma.rn.f32x2 %0, %1, %2, %3;" : "=l"(d) : "l"(a), "l"(b), "l"(c))
#define DUP_F32X2(d, x) \
    asm("mov.b64 %0, {%1, %1};" : "=l"(d) : "r"(x))
__device__ __forceinline__ float lo32(u64 v) { return __uint_as_float((unsigned)(v & 0xFFFFFFFFu)); }
__device__ __forceinline__ float hi32(u64 v) { return __uint_as_float((unsigned)(v >> 32)); }

// ---------------------------------------------------------------------------
// Bit-exact row norms (XLA order): warp/row, lane t sums t+32i, mul+add, shfl tree
// ---------------------------------------------------------------------------
__device__ __forceinline__ float row_sumsq_warp(const float* __restrict__ row, int lane) {
    float s = 0.f;
#pragma unroll
    for (int i = 0; i < DIM / 32; ++i) {
        float v = row[lane + i * 32];
        s = __fadd_rn(s, __fmul_rn(v, v));
    }
#pragma unroll
    for (int o = 16; o > 0; o >>= 1)
        s = __fadd_rn(s, __shfl_down_sync(0xFFFFFFFFu, s, o));
    return s;
}

__global__ void norms_kernel(const float* __restrict__ z, const float* __restrict__ cb) {
    int warp = (blockIdx.x * blockDim.x + threadIdx.x) >> 5;
    int lane = threadIdx.x & 31;
    if (warp == 0 && lane == 0) { g_loss = 0.0; g_nflag = 0; }
    if (warp < N_ROWS) {
        float s = row_sumsq_warp(z + (size_t)warp * DIM, lane);
        if (lane == 0) g_zn[warp] = s;
    }
    if (warp < KCB) {
        float s = row_sumsq_warp(cb + (size_t)warp * DIM, lane);
        if (lane == 0) g_cnorm[warp] = s;
    }
}

// ---------------------------------------------------------------------------
// Screening: wmma bf16 (fp32 accumulate) distance GEMM + per-row top-2.
// CTA = 256 threads (8 warps), 128 rows, all 1024 codes, K=256.
// Warp w owns rows 16w..16w+15; lane<16 owns row 16w+lane's top-2 state.
// ---------------------------------------------------------------------------
#define LDZ 264                      // bf16 leading dim (mult of 8), spreads banks
#define S_Z   0                      // z tile bf16 [128][LDZ]
#define S_CB  67584                  // cb chunk bf16 [128][LDZ]
#define S_CN  135168                 // cnorm f32 [1024]
#define S_SCR 139264                 // scratch f32 [8 warps][16][20]
#define S_TOT 149504

__global__ void __launch_bounds__(256)
screen_kernel(const float* __restrict__ z, const float* __restrict__ cb) {
    extern __shared__ char smem[];
    __nv_bfloat16* zt  = (__nv_bfloat16*)(smem + S_Z);
    __nv_bfloat16* cbt = (__nv_bfloat16*)(smem + S_CB);
    float* cn_s = (float*)(smem + S_CN);

    const int tid = threadIdx.x, w = tid >> 5, lane = tid & 31;
    const int blockRow = blockIdx.x * 128;
    float (*scr)[20] = (float(*)[20])(smem + S_SCR + w * 16 * 20 * 4);

    for (int t = tid; t < KCB; t += 256) cn_s[t] = g_cnorm[t];

    // stage z tile -> bf16 smem
    for (int t = tid; t < 128 * 32; t += 256) {
        int row = t >> 5, c8 = t & 31;
        const float4* p = (const float4*)&z[(size_t)(blockRow + row) * DIM + c8 * 8];
        float4 a = p[0], b = p[1];
        __nv_bfloat162 h0 = __floats2bfloat162_rn(a.x, a.y), h1 = __floats2bfloat162_rn(a.z, a.w);
        __nv_bfloat162 h2 = __floats2bfloat162_rn(b.x, b.y), h3 = __floats2bfloat162_rn(b.z, b.w);
        uint4 u;
        u.x = *(uint32_t*)&h0; u.y = *(uint32_t*)&h1;
        u.z = *(uint32_t*)&h2; u.w = *(uint32_t*)&h3;
        *(uint4*)&zt[row * LDZ + c8 * 8] = u;
    }

    float best = 3.4e38f, best2 = 3.4e38f;
    int   bidx = 0;

#pragma unroll 1
    for (int c = 0; c < 8; ++c) {
        __syncthreads();    // retire prior chunk's reads of cbt
        for (int t = tid; t < 128 * 32; t += 256) {
            int row = t >> 5, c8 = t & 31;
            const float4* p = (const float4*)&cb[(size_t)(c * 128 + row) * DIM + c8 * 8];
            float4 a = p[0], b = p[1];
            __nv_bfloat162 h0 = __floats2bfloat162_rn(a.x, a.y), h1 = __floats2bfloat162_rn(a.z, a.w);
            __nv_bfloat162 h2 = __floats2bfloat162_rn(b.x, b.y), h3 = __floats2bfloat162_rn(b.z, b.w);
            uint4 u;
            u.x = *(uint32_t*)&h0; u.y = *(uint32_t*)&h1;
            u.z = *(uint32_t*)&h2; u.w = *(uint32_t*)&h3;
            *(uint4*)&cbt[row * LDZ + c8 * 8] = u;
        }
        __syncthreads();

        wmma::fragment<wmma::accumulator, 16, 16, 16, float> facc[8];
#pragma unroll
        for (int ns = 0; ns < 8; ++ns) wmma::fill_fragment(facc[ns], 0.0f);

#pragma unroll 1
        for (int ks = 0; ks < 16; ++ks) {
            wmma::fragment<wmma::matrix_a, 16, 16, 16, __nv_bfloat16, wmma::row_major> fa;
            wmma::load_matrix_sync(fa, zt + (16 * w) * LDZ + 16 * ks, LDZ);
#pragma unroll
            for (int ns = 0; ns < 8; ++ns) {
                wmma::fragment<wmma::matrix_b, 16, 16, 16, __nv_bfloat16, wmma::col_major> fb;
                wmma::load_matrix_sync(fb, cbt + (16 * ns) * LDZ + 16 * ks, LDZ);
                wmma::mma_sync(facc[ns], fa, fb, facc[ns]);
            }
        }

#pragma unroll 1
        for (int ns = 0; ns < 8; ++ns) {
            wmma::store_matrix_sync(&scr[0][0], facc[ns], 20, wmma::mem_row_major);
            __syncwarp();
            if (lane < 16) {
#pragma unroll
                for (int j = 0; j < 16; ++j) {
                    int k = c * 128 + ns * 16 + j;
                    float v = fmaf(-2.f, scr[lane][j], cn_s[k]);
                    if (v < best) { best2 = best; best = v; bidx = k; }
                    else if (v < best2) best2 = v;
                }
            }
            __syncwarp();
        }
    }

    if (lane < 16) {
        int row = blockRow + w * 16 + lane;
        g_ids[row] = bidx;
        if (best2 - best < DELTA) {
            int p = atomicAdd(&g_nflag, 1);
            g_flagged[p] = row;
        }
    }
}

// ---------------------------------------------------------------------------
// Exact rescue: bit-exact FFMA2 GEMM-argmin on flagged rows (row indirection)
// ---------------------------------------------------------------------------
__global__ void __launch_bounds__(256, 2)
rescue_kernel(const float* __restrict__ z, const float* __restrict__ cb) {
    __shared__ __align__(16) float zs[BD][BM + PAD];
    __shared__ __align__(16) float cs[BD][BN + PAD];
    __shared__ float zn_s[BM];
    __shared__ int   ridx_s[BM];

    const int nf = g_nflag;
    const int blockRow = blockIdx.x * BM;
    if (blockRow >= nf) return;

    const int tid = threadIdx.x;
    const int tx = tid & 15;
    const int ty = tid >> 4;

    if (tid < BM) {
        int s = blockRow + tid;
        int r = g_flagged[(s < nf) ? s : blockRow];
        ridx_s[tid] = r;
        zn_s[tid] = g_zn[r];
    }

    float bestv[8];
    int   besti[8];
#pragma unroll
    for (int i = 0; i < 8; ++i) { bestv[i] = 3.4e38f; besti[i] = 0; }

    const int c4 = tid & 7;
    const int r0 = tid >> 3;

#pragma unroll 1
    for (int kt = 0; kt < KCB; kt += BN) {
        u64 acc[4][8];
#pragma unroll
        for (int p = 0; p < 4; ++p)
#pragma unroll
            for (int j = 0; j < 8; ++j) acc[p][j] = 0ull;

#pragma unroll 1
        for (int dt = 0; dt < DIM; dt += BD) {
            __syncthreads();
#pragma unroll
            for (int q = 0; q < 4; ++q) {
                int r = q * 32 + r0;
                float4 v = *(const float4*)&z[(size_t)ridx_s[r] * DIM + dt + c4 * 4];
                zs[c4 * 4 + 0][r] = v.x; zs[c4 * 4 + 1][r] = v.y;
                zs[c4 * 4 + 2][r] = v.z; zs[c4 * 4 + 3][r] = v.w;
                float4 w = *(const float4*)&cb[(size_t)(kt + r) * DIM + dt + c4 * 4];
                cs[c4 * 4 + 0][r] = w.x; cs[c4 * 4 + 1][r] = w.y;
                cs[c4 * 4 + 2][r] = w.z; cs[c4 * 4 + 3][r] = w.w;
            }
            __syncthreads();

#pragma unroll 8
            for (int d = 0; d < BD; ++d) {
                u64 zap[4];
#pragma unroll
                for (int p = 0; p < 4; ++p)
                    zap[p] = *(const u64*)&zs[d][ty * 8 + 2 * p];
                u64 cdup[8];
#pragma unroll
                for (int j = 0; j < 8; ++j) {
                    float cc = cs[d][tx + 16 * j];
                    DUP_F32X2(cdup[j], __float_as_uint(cc));
                }
#pragma unroll
                for (int p = 0; p < 4; ++p)
#pragma unroll
                    for (int j = 0; j < 8; ++j)
                        FMA_F32X2(acc[p][j], zap[p], cdup[j], acc[p][j]);
            }
        }

#pragma unroll
        for (int j = 0; j < 8; ++j) {
            int kk = kt + tx + 16 * j;
            float cn = g_cnorm[kk];
#pragma unroll
            for (int p = 0; p < 4; ++p) {
                float a0 = lo32(acc[p][j]);
                float a1 = hi32(acc[p][j]);
                int i0 = 2 * p, i1 = 2 * p + 1;
                float s0 = fmaf(-2.f, a0, zn_s[ty * 8 + i0]);
                float v0 = __fadd_rn(s0, cn);
                if (v0 < bestv[i0]) { bestv[i0] = v0; besti[i0] = kk; }
                float s1 = fmaf(-2.f, a1, zn_s[ty * 8 + i1]);
                float v1 = __fadd_rn(s1, cn);
                if (v1 < bestv[i1]) { bestv[i1] = v1; besti[i1] = kk; }
            }
        }
    }

    __syncthreads();
    float* redv = &zs[0][0];
    int*   redi = (int*)&cs[0][0];
#pragma unroll
    for (int i = 0; i < 8; ++i) {
        redv[(ty * 8 + i) * 16 + tx] = bestv[i];
        redi[(ty * 8 + i) * 16 + tx] = besti[i];
    }
    __syncthreads();
    if (tid < BM && blockRow + tid < nf) {
        float bv = redv[tid * 16];
        int   bi = redi[tid * 16];
#pragma unroll
        for (int t = 1; t < 16; ++t) {
            float v = redv[tid * 16 + t];
            int   ii = redi[tid * 16 + t];
            if (v < bv || (v == bv && ii < bi)) { bv = v; bi = ii; }
        }
        g_ids[ridx_s[tid]] = bi;
    }
}

// ---------------------------------------------------------------------------
// Outputs: z | z_q_st = z + (z_q - z) | ids | loss
// ---------------------------------------------------------------------------
__global__ void output_kernel(const float* __restrict__ z,
                              const float* __restrict__ cb,
                              float* __restrict__ out) {
    const size_t ND = (size_t)N_ROWS * DIM;
    int gtid = blockIdx.x * blockDim.x + threadIdx.x;
    size_t base = (size_t)gtid * 4;

    float local = 0.f;
    if (base < ND) {
        int n = (int)(base / DIM);
        int d = (int)(base % DIM);
        float4 zv = *(const float4*)&z[base];
        int id = g_ids[n];
        float4 cv = *(const float4*)&cb[(size_t)id * DIM + d];
        *(float4*)&out[base] = zv;
        float tx_ = __fadd_rn(cv.x, -zv.x), ty_ = __fadd_rn(cv.y, -zv.y);
        float tz_ = __fadd_rn(cv.z, -zv.z), tw_ = __fadd_rn(cv.w, -zv.w);
        float4 st;
        st.x = __fadd_rn(zv.x, tx_); st.y = __fadd_rn(zv.y, ty_);
        st.z = __fadd_rn(zv.z, tz_); st.w = __fadd_rn(zv.w, tw_);
        *(float4*)&out[ND + base] = st;
        local = tx_ * tx_ + ty_ * ty_ + tz_ * tz_ + tw_ * tw_;
    }
    if (gtid < N_ROWS) out[2 * ND + gtid] = (float)g_ids[gtid];

    __shared__ float warp_s[8];
#pragma unroll
    for (int o = 16; o > 0; o >>= 1)
        local += __shfl_down_sync(0xFFFFFFFFu, local, o);
    if ((threadIdx.x & 31) == 0) warp_s[threadIdx.x >> 5] = local;
    __syncthreads();
    if (threadIdx.x < 8) {
        float v = warp_s[threadIdx.x];
#pragma unroll
        for (int o = 4; o > 0; o >>= 1)
            v += __shfl_down_sync(0xFFu, v, o);
        if (threadIdx.x == 0 && v != 0.f) atomicAdd(&g_loss, (double)v);
    }
}

__global__ void finalize_kernel(float* __restrict__ out) {
    const size_t ND = (size_t)N_ROWS * DIM;
    out[2 * ND + N_ROWS] = (float)(1.25 * g_loss / (double)ND);
}

// ---------------------------------------------------------------------------
extern "C" void kernel_launch(void* const* d_in, const int* in_sizes, int n_in,
                              void* d_out, int out_size) {
    const float* z  = (const float*)d_in[0];
    const float* cb = (const float*)d_in[1];
    float* out = (float*)d_out;

    cudaFuncSetAttribute(screen_kernel, cudaFuncAttributeMaxDynamicSharedMemorySize, S_TOT);

    norms_kernel<<<(N_ROWS * 32 + 255) / 256, 256>>>(z, cb);
    screen_kernel<<<N_ROWS / 128, 256, S_TOT>>>(z, cb);
    rescue_kernel<<<N_ROWS / BM, 256>>>(z, cb);
    const size_t ND = (size_t)N_ROWS * DIM;
    int nblk = (int)((ND / 4 + 255) / 256);
    output_kernel<<<nblk, 256>>>(z, cb, out);
    finalize_kernel<<<1, 1>>>(out);
}